// round 16
// baseline (speedup 1.0000x reference)
#include <cuda_runtime.h>
#include <cuda_fp16.h>
#include <cstdint>

#define BATCH 8
#define CH    16
#define HH    256
#define WW    256
#define HW    (HH*WW)
#define NPTS  (BATCH*HH*WW)              // 524288 grid points / output cells
#define SCRATCH_U4 (NPTS*2)              // cell = 16 half = 32B = 2 uint4; 16.7 MB

// f16 scratch accumulator, channels innermost: [b][i][j][c(half)].
// Zero at module load; transpose_kernel restores zeros after reading, so the
// scratch is zero at the start of EVERY kernel_launch call (deterministic
// across correctness run, capture, and all graph replays).
__device__ uint4 g_scratchv[SCRATCH_U4];

// ---------------------------------------------------------------------------
// Kernel 1: scatter, 2 consecutive (same-b) points per thread, 256 thr/block
// (8192 warps -> 2 waves/SM, saturates the L2 atomic path).
// Per tap: 1 FMUL + 8 HMUL2 + 2x red.global.add.noftz.v4.f16x2 (16B each).
// At the L2 atomic-op floor: 8.39M REDs / 192 LTS slices ~ 22us. Frozen.
// ---------------------------------------------------------------------------
__global__ void __launch_bounds__(256) scatter_kernel(
    const float2* __restrict__ x2, const float4* __restrict__ grid4)
{
    int t = blockIdx.x * blockDim.x + threadIdx.x;   // 0 .. NPTS/2-1
    int b   = t >> 15;                               // (2t) >> 16
    int hw2 = t & 0x7FFF;                            // hw/2

    // grid: [b][h][w][2] -> 2 points = 1 float4: p0:(x,y) p1:(x,y)
    float4 g = grid4[t];
    float gx[2] = {g.x, g.z};
    float gy[2] = {g.y, g.w};

    // x: [b][c][h][w]; one float2 per channel covers both points.
    const float2* xp = x2 + ((size_t)b * (CH * HW) >> 1) + hw2;
    float2 xv[CH];
#pragma unroll
    for (int c = 0; c < CH; c++) xv[c] = xp[(size_t)c * (HW / 2)];

    // xh[p][cp] = half2(x[2cp], x[2cp+1]) for point p  (16 regs)
    __half2 xh[2][8];
#pragma unroll
    for (int cp = 0; cp < 8; cp++) {
        xh[0][cp] = __floats2half2_rn(xv[2*cp].x, xv[2*cp+1].x);
        xh[1][cp] = __floats2half2_rn(xv[2*cp].y, xv[2*cp+1].y);
    }

    char* sbase = reinterpret_cast<char*>(g_scratchv);

#pragma unroll
    for (int p = 0; p < 2; p++) {
        float ci = fminf(fmaxf((gx[p] + 1.0f) * 0.5f * 256.0f + 1.0f, 0.0f), 257.0f);
        float cj = fminf(fmaxf((gy[p] + 1.0f) * 0.5f * 256.0f + 1.0f, 0.0f), 257.0f);

        float fi0 = floorf(ci), fj0 = floorf(cj);
        int   i0 = (int)fi0,    j0 = (int)fj0;
        float fi = ci - fi0,    fj = cj - fj0;       // in [0,1)

        float wi[2] = {1.0f - fi, fi};
        float wj[2] = {1.0f - fj, fj};

#pragma unroll
        for (int di = 0; di < 2; di++) {
            int oi = i0 + di - 1;
            if ((unsigned)oi >= 256u) continue;
#pragma unroll
            for (int dj = 0; dj < 2; dj++) {
                int oj = j0 + dj - 1;
                if ((unsigned)oj >= 256u) continue;
                __half2 wt2 = __float2half2_rn(wi[di] * wj[dj]);
                size_t cell = ((((size_t)b << 8 | oi) << 8 | oj) << 5);  // *32B
#pragma unroll
                for (int k = 0; k < 2; k++) {
                    __half2 h0 = __hmul2(xh[p][4*k + 0], wt2);
                    __half2 h1 = __hmul2(xh[p][4*k + 1], wt2);
                    __half2 h2 = __hmul2(xh[p][4*k + 2], wt2);
                    __half2 h3 = __hmul2(xh[p][4*k + 3], wt2);
                    asm volatile(
                        "red.global.add.noftz.v4.f16x2 [%0], {%1, %2, %3, %4};"
                        :: "l"(sbase + cell + 16*k),
                           "r"(*(unsigned*)&h0), "r"(*(unsigned*)&h1),
                           "r"(*(unsigned*)&h2), "r"(*(unsigned*)&h3)
                        : "memory");
                }
            }
        }
    }
}

// ---------------------------------------------------------------------------
// Kernel 2: transpose f16 scratch [b][i][j][c] -> f32 out [b][c][i][j],
// restoring each scratch cell to zero right after reading it (contiguous
// 128B store-and-forget; replaces the 5.8us dedicated zero pass).
// Thread owns 4 consecutive cells (128B contiguous load), assembles
// per-channel float4 in registers, 16 coalesced STG.128 to out.
// ---------------------------------------------------------------------------
__global__ void __launch_bounds__(256) transpose_kernel(float* __restrict__ out) {
    int tid = threadIdx.x;
    int r   = tid >> 6;                      // row within block (0..3)
    int q   = tid & 63;                      // j-quad (0..63), j0 = 4q
    int bi  = blockIdx.x * 4 + r;            // b*256 + i
    int b = bi >> 8, i = bi & 255;

    // 4 cells = 8 uint4, contiguous.
    uint4* src = g_scratchv + (size_t)bi * 512 + q * 8;
    uint4 cv[8];
#pragma unroll
    for (int m = 0; m < 8; m++) cv[m] = src[m];

    // Restore zeros for the next call (8 contiguous STG.128).
    const uint4 z = make_uint4(0u, 0u, 0u, 0u);
#pragma unroll
    for (int m = 0; m < 8; m++) src[m] = z;

    float* op = out + ((size_t)b * CH * HH + i) * WW + 4 * q;
#pragma unroll
    for (int c = 0; c < CH; c++) {
        float v[4];
#pragma unroll
        for (int m = 0; m < 4; m++) {
            uint4 u = cv[2*m + (c >> 3)];
            int sel = (c >> 1) & 3;
            unsigned wbits = sel == 0 ? u.x : sel == 1 ? u.y : sel == 2 ? u.z : u.w;
            __half2 h = *reinterpret_cast<__half2*>(&wbits);
            float2 f = __half22float2(h);
            v[m] = (c & 1) ? f.y : f.x;
        }
        *reinterpret_cast<float4*>(op + (size_t)c * HW) =
            make_float4(v[0], v[1], v[2], v[3]);
    }
}

// ---------------------------------------------------------------------------
extern "C" void kernel_launch(void* const* d_in, const int* in_sizes, int n_in,
                              void* d_out, int out_size)
{
    const float* x    = (const float*)d_in[0];
    const float* grid = (const float*)d_in[1];
    if (in_sizes[0] != BATCH * CH * HW) {     // pick by size, defensively
        const float* t = x; x = grid; grid = t;
    }

    scatter_kernel<<<(NPTS / 2) / 256, 256>>>((const float2*)x, (const float4*)grid);
    transpose_kernel<<<(BATCH * HH) / 4, 256>>>((float*)d_out);
}